// round 1
// baseline (speedup 1.0000x reference)
#include <cuda_runtime.h>

// Problem constants
#define BB 4
#define SS 2048
#define HH 1024
#define NH 16
#define HD 64
#define NROWS (BB*SS)          // 8192
#define GKDIM HH               // K of all GEMMs
#define CHUNK 64
#define NCHUNK (SS/CHUNK)      // 32
#define BHDIM (BB*NH)          // 64
#define SE (HD*HD)             // 4096 state elems per (b,h)

// ---------------- scratch (static __device__, allocation-free) ----------------
__device__ __align__(16) float g_q[(size_t)NROWS*HH];
__device__ __align__(16) float g_k[(size_t)NROWS*HH];
__device__ __align__(16) float g_v[(size_t)NROWS*HH];
__device__ __align__(16) float g_g[(size_t)NROWS*HH];
__device__ __align__(16) float g_attn[(size_t)NROWS*HH];
__device__ float g_alpha[NROWS*NH];
__device__ float g_beta[NROWS*NH];
__device__ __align__(16) float g_M [(size_t)BHDIM*NCHUNK*SE];
__device__ __align__(16) float g_Cc[(size_t)BHDIM*NCHUNK*SE];
__device__ __align__(16) float g_S0[(size_t)BHDIM*NCHUNK*SE];

__device__ __forceinline__ float sigmoidf_(float z){ return 1.f/(1.f+expf(-z)); }

// ---------------- GEMM: C[M,N] = A[M,K] * W[N,K]^T  (both K-contiguous) ------
// 128x128 tile, BK=16, 256 threads, 8x8 per thread, double-buffered smem.
#define BKD 16
__global__ void __launch_bounds__(256,2) gemm_nt_kernel(
    const float* __restrict__ Aext, int asel,
    const float* __restrict__ W,
    float* __restrict__ Cext, int csel, int epi)
{
    __shared__ __align__(16) float As[2][BKD][128];
    __shared__ __align__(16) float Bs[2][BKD][128];

    const float* A = asel ? g_attn : Aext;
    float* Cout;
    switch (csel){
        case 0: Cout = g_q;  break;
        case 1: Cout = g_k;  break;
        case 2: Cout = g_v;  break;
        case 3: Cout = g_g;  break;
        default: Cout = Cext; break;
    }

    const int tid = threadIdx.x;
    const int tx = tid & 15;
    const int ty = tid >> 4;
    const int m0 = blockIdx.y * 128;
    const int n0 = blockIdx.x * 128;

    const int lr = tid >> 1;          // 0..127
    const int lk = (tid & 1) * 8;     // 0 or 8
    const float* Ap = A + (size_t)(m0 + lr) * GKDIM + lk;
    const float* Wp = W + (size_t)(n0 + lr) * GKDIM + lk;

    float acc[8][8];
    #pragma unroll
    for (int i=0;i<8;i++)
        #pragma unroll
        for (int j=0;j<8;j++) acc[i][j] = 0.f;

    // prologue: load tile 0
    {
        float4 a0 = *(const float4*)(Ap);
        float4 a1 = *(const float4*)(Ap + 4);
        float4 b0 = *(const float4*)(Wp);
        float4 b1 = *(const float4*)(Wp + 4);
        As[0][lk+0][lr]=a0.x; As[0][lk+1][lr]=a0.y; As[0][lk+2][lr]=a0.z; As[0][lk+3][lr]=a0.w;
        As[0][lk+4][lr]=a1.x; As[0][lk+5][lr]=a1.y; As[0][lk+6][lr]=a1.z; As[0][lk+7][lr]=a1.w;
        Bs[0][lk+0][lr]=b0.x; Bs[0][lk+1][lr]=b0.y; Bs[0][lk+2][lr]=b0.z; Bs[0][lk+3][lr]=b0.w;
        Bs[0][lk+4][lr]=b1.x; Bs[0][lk+5][lr]=b1.y; Bs[0][lk+6][lr]=b1.z; Bs[0][lk+7][lr]=b1.w;
    }
    __syncthreads();

    const int NT = GKDIM / BKD;  // 64
    for (int kt = 0; kt < NT; ++kt){
        const int cur = kt & 1;
        float4 a0,a1,b0,b1;
        if (kt + 1 < NT){
            const float* Ap2 = Ap + (kt+1)*BKD;
            const float* Wp2 = Wp + (kt+1)*BKD;
            a0 = *(const float4*)(Ap2);
            a1 = *(const float4*)(Ap2 + 4);
            b0 = *(const float4*)(Wp2);
            b1 = *(const float4*)(Wp2 + 4);
        }
        #pragma unroll
        for (int kk=0; kk<BKD; ++kk){
            const float4* arow = reinterpret_cast<const float4*>(As[cur][kk]);
            const float4* brow = reinterpret_cast<const float4*>(Bs[cur][kk]);
            float4 af0 = arow[ty], af1 = arow[ty+16];
            float4 bf0 = brow[tx], bf1 = brow[tx+16];
            float av[8] = {af0.x,af0.y,af0.z,af0.w, af1.x,af1.y,af1.z,af1.w};
            float bv[8] = {bf0.x,bf0.y,bf0.z,bf0.w, bf1.x,bf1.y,bf1.z,bf1.w};
            #pragma unroll
            for (int i=0;i<8;i++)
                #pragma unroll
                for (int j=0;j<8;j++)
                    acc[i][j] = fmaf(av[i], bv[j], acc[i][j]);
        }
        if (kt + 1 < NT){
            const int nxt = cur ^ 1;
            As[nxt][lk+0][lr]=a0.x; As[nxt][lk+1][lr]=a0.y; As[nxt][lk+2][lr]=a0.z; As[nxt][lk+3][lr]=a0.w;
            As[nxt][lk+4][lr]=a1.x; As[nxt][lk+5][lr]=a1.y; As[nxt][lk+6][lr]=a1.z; As[nxt][lk+7][lr]=a1.w;
            Bs[nxt][lk+0][lr]=b0.x; Bs[nxt][lk+1][lr]=b0.y; Bs[nxt][lk+2][lr]=b0.z; Bs[nxt][lk+3][lr]=b0.w;
            Bs[nxt][lk+4][lr]=b1.x; Bs[nxt][lk+5][lr]=b1.y; Bs[nxt][lk+6][lr]=b1.z; Bs[nxt][lk+7][lr]=b1.w;
            __syncthreads();
        }
    }

    // epilogue: rows {ty*4+0..3, 64+ty*4+0..3}, cols {tx*4+0..3, 64+tx*4+0..3}
    #pragma unroll
    for (int i=0;i<8;i++){
        const int r = m0 + ((i<4) ? (ty*4 + i) : (64 + ty*4 + (i-4)));
        float* crow = Cout + (size_t)r * HH + n0;
        float vv[8];
        #pragma unroll
        for (int j=0;j<8;j++){
            float v = acc[i][j];
            if (epi) v = v * sigmoidf_(v);   // SiLU
            vv[j] = v;
        }
        *(float4*)(crow + tx*4)       = make_float4(vv[0],vv[1],vv[2],vv[3]);
        *(float4*)(crow + 64 + tx*4)  = make_float4(vv[4],vv[5],vv[6],vv[7]);
    }
}

// ---------------- alpha/beta: sigmoid(x @ [Wa;Wb]^T + bias) ------------------
__global__ void __launch_bounds__(256) ab_kernel(
    const float* __restrict__ x,
    const float* __restrict__ Wa, const float* __restrict__ ba,
    const float* __restrict__ Wb, const float* __restrict__ bb)
{
    __shared__ float xs[HH];
    __shared__ float part[32][9];
    const int r = blockIdx.x, tid = threadIdx.x;
    for (int i=tid;i<HH;i+=256) xs[i] = x[(size_t)r*HH + i];
    __syncthreads();
    const int o = tid >> 3, sl = tid & 7;
    const float* wrow = (o < NH) ? (Wa + (size_t)o*HH) : (Wb + (size_t)(o-NH)*HH);
    float p = 0.f;
    const int k0 = sl * 128;
    #pragma unroll 8
    for (int kk=0; kk<128; ++kk) p = fmaf(xs[k0+kk], wrow[k0+kk], p);
    part[o][sl] = p;
    __syncthreads();
    if (tid < 32){
        float s = 0.f;
        #pragma unroll
        for (int j=0;j<8;j++) s += part[tid][j];
        s += (tid < NH) ? ba[tid] : bb[tid-NH];
        s = sigmoidf_(s);
        if (tid < NH) g_alpha[r*NH + tid] = s;
        else          g_beta [r*NH + tid - NH] = s;
    }
}

// ---------------- per-head L2 normalization (in place) -----------------------
__global__ void __launch_bounds__(256) l2norm_kernel(int sel)
{
    float* base = sel ? g_k : g_q;
    const int gw = (blockIdx.x*blockDim.x + threadIdx.x) >> 5;
    const int l = threadIdx.x & 31;
    if (gw >= NROWS*NH) return;
    float* v = base + (size_t)gw * HD;
    float a = v[l], b = v[l+32];
    float ss = fmaf(a, a, b*b);
    #pragma unroll
    for (int o=16;o;o>>=1) ss += __shfl_xor_sync(0xffffffffu, ss, o);
    const float inv = 1.f / fmaxf(sqrtf(ss), 1e-12f);
    v[l]    = a * inv;
    v[l+32] = b * inv;
}

// ---------------- recurrence pass 1: per-chunk transitions -------------------
// state[i,j] <- m*state + c ; m = a - a*b*k_i*k_j ; c = b*v_i*k_j
// block = (chunk, bh); 512 thr: warp w owns rows 4w..4w+3, lane l cols {l,l+32}
__global__ void __launch_bounds__(512) pass1_kernel()
{
    const int c = blockIdx.x, bh = blockIdx.y;
    const int b = bh >> 4, h = bh & 15;
    const int tid = threadIdx.x;
    const int w = tid >> 5, l = tid & 31;
    __shared__ float ks[HD], vs[HD], sab[2];
    float M[4][2], Cc[4][2];
    #pragma unroll
    for (int r=0;r<4;r++){ M[r][0]=1.f; M[r][1]=1.f; Cc[r][0]=0.f; Cc[r][1]=0.f; }
    const int row0 = b*SS + c*CHUNK;
    for (int t=0;t<CHUNK;++t){
        const int row = row0 + t;
        __syncthreads();
        if (tid < 64)        ks[tid]     = g_k[(size_t)row*HH + h*HD + tid];
        else if (tid < 128)  vs[tid-64]  = g_v[(size_t)row*HH + h*HD + (tid-64)];
        else if (tid == 128) sab[0] = g_alpha[row*NH + h];
        else if (tid == 129) sab[1] = g_beta [row*NH + h];
        __syncthreads();
        const float a = sab[0], bt = sab[1], abp = a*bt;
        const float kj0 = ks[l], kj1 = ks[l+32];
        #pragma unroll
        for (int r=0;r<4;r++){
            const int i = w*4 + r;
            const float ki = ks[i];
            const float bvi = bt * vs[i];
            const float abki = abp * ki;
            const float m0 = fmaf(-abki, kj0, a);
            const float m1 = fmaf(-abki, kj1, a);
            M[r][0] *= m0;  M[r][1] *= m1;
            Cc[r][0] = fmaf(m0, Cc[r][0], bvi*kj0);
            Cc[r][1] = fmaf(m1, Cc[r][1], bvi*kj1);
        }
    }
    const size_t ob = ((size_t)bh*NCHUNK + c) * SE;
    #pragma unroll
    for (int r=0;r<4;r++){
        const int i = w*4 + r;
        g_M [ob + i*HD + l]      = M[r][0];
        g_M [ob + i*HD + l + 32] = M[r][1];
        g_Cc[ob + i*HD + l]      = Cc[r][0];
        g_Cc[ob + i*HD + l + 32] = Cc[r][1];
    }
}

// ---------------- serial scan over chunks (depth 32, 8 chains/thread) --------
__global__ void __launch_bounds__(512) scan_kernel()
{
    const int bh = blockIdx.x;
    const size_t base = (size_t)bh * NCHUNK * SE;
    float s[8];
    #pragma unroll
    for (int u=0;u<8;u++) s[u] = 0.f;
    for (int c=0;c<NCHUNK;++c){
        const size_t cb = base + (size_t)c*SE + threadIdx.x;
        #pragma unroll
        for (int u=0;u<8;u++){
            const size_t idx = cb + (size_t)u*512;
            g_S0[idx] = s[u];
            s[u] = fmaf(g_M[idx], s[u], g_Cc[idx]);
        }
    }
}

// ---------------- recurrence pass 2: replay chunks + output reduction --------
__global__ void __launch_bounds__(512) pass2_kernel()
{
    const int c = blockIdx.x, bh = blockIdx.y;
    const int b = bh >> 4, h = bh & 15;
    const int tid = threadIdx.x;
    const int w = tid >> 5, l = tid & 31;
    __shared__ float ks[HD], vs[HD], qs[HD], sab[2];
    float st[4][2];
    const size_t sb = ((size_t)bh*NCHUNK + c) * SE;
    #pragma unroll
    for (int r=0;r<4;r++){
        const int i = w*4 + r;
        st[r][0] = g_S0[sb + i*HD + l];
        st[r][1] = g_S0[sb + i*HD + l + 32];
    }
    const int row0 = b*SS + c*CHUNK;
    for (int t=0;t<CHUNK;++t){
        const int row = row0 + t;
        __syncthreads();
        if (tid < 64)        ks[tid]      = g_k[(size_t)row*HH + h*HD + tid];
        else if (tid < 128)  vs[tid-64]   = g_v[(size_t)row*HH + h*HD + (tid-64)];
        else if (tid < 192)  qs[tid-128]  = g_q[(size_t)row*HH + h*HD + (tid-128)];
        else if (tid == 192) sab[0] = g_alpha[row*NH + h];
        else if (tid == 193) sab[1] = g_beta [row*NH + h];
        __syncthreads();
        const float a = sab[0], bt = sab[1], abp = a*bt;
        const float kj0 = ks[l], kj1 = ks[l+32];
        const float qj0 = qs[l], qj1 = qs[l+32];
        float p[4];
        #pragma unroll
        for (int r=0;r<4;r++){
            const int i = w*4 + r;
            const float ki = ks[i];
            const float bvi = bt * vs[i];
            const float abki = abp * ki;
            const float m0 = fmaf(-abki, kj0, a);
            const float m1 = fmaf(-abki, kj1, a);
            st[r][0] = fmaf(m0, st[r][0], bvi*kj0);
            st[r][1] = fmaf(m1, st[r][1], bvi*kj1);
            p[r] = fmaf(st[r][0], qj0, st[r][1]*qj1);
        }
        #pragma unroll
        for (int o=16;o;o>>=1){
            p[0] += __shfl_xor_sync(0xffffffffu, p[0], o);
            p[1] += __shfl_xor_sync(0xffffffffu, p[1], o);
            p[2] += __shfl_xor_sync(0xffffffffu, p[2], o);
            p[3] += __shfl_xor_sync(0xffffffffu, p[3], o);
        }
        if (l < 4) g_attn[(size_t)row*HH + h*HD + w*4 + l] = p[l];
    }
}

// ---------------- LayerNorm + SiLU-gate (in place on g_attn) -----------------
__global__ void __launch_bounds__(256) ln_gate_kernel(
    const float* __restrict__ lng, const float* __restrict__ lnb)
{
    const int r = blockIdx.x, tid = threadIdx.x;
    __shared__ float xs[HH];
    __shared__ float red[8];
    float* row = g_attn + (size_t)r*HH;
    float s = 0.f;
    for (int i=tid;i<HH;i+=256){ float v = row[i]; xs[i] = v; s += v; }
    #pragma unroll
    for (int o=16;o;o>>=1) s += __shfl_xor_sync(0xffffffffu, s, o);
    if ((tid & 31) == 0) red[tid>>5] = s;
    __syncthreads();
    float tot = red[0]+red[1]+red[2]+red[3]+red[4]+red[5]+red[6]+red[7];
    const float mu = tot * (1.f/HH);
    __syncthreads();
    float vsum = 0.f;
    for (int i=tid;i<HH;i+=256){ float d = xs[i]-mu; vsum = fmaf(d,d,vsum); }
    #pragma unroll
    for (int o=16;o;o>>=1) vsum += __shfl_xor_sync(0xffffffffu, vsum, o);
    if ((tid & 31) == 0) red[tid>>5] = vsum;
    __syncthreads();
    float vtot = red[0]+red[1]+red[2]+red[3]+red[4]+red[5]+red[6]+red[7];
    const float rstd = rsqrtf(vtot*(1.f/HH) + 1e-5f);
    for (int i=tid;i<HH;i+=256){
        const float y = (xs[i]-mu)*rstd*lng[i] + lnb[i];
        row[i] = y * g_g[(size_t)r*HH + i];
    }
}

// ---------------- launch -----------------------------------------------------
extern "C" void kernel_launch(void* const* d_in, const int* in_sizes, int n_in,
                              void* d_out, int out_size)
{
    const float* x   = (const float*)d_in[0];
    const float* Wq  = (const float*)d_in[1];
    const float* Wk  = (const float*)d_in[2];
    const float* Wv  = (const float*)d_in[3];
    const float* Wa  = (const float*)d_in[4];
    const float* ba  = (const float*)d_in[5];
    const float* Wb  = (const float*)d_in[6];
    const float* bb  = (const float*)d_in[7];
    const float* Wg  = (const float*)d_in[8];
    const float* Wo  = (const float*)d_in[9];
    const float* lng = (const float*)d_in[10];
    const float* lnb = (const float*)d_in[11];
    float* out = (float*)d_out;

    dim3 gg(HH/128, NROWS/128);   // (8, 64)
    gemm_nt_kernel<<<gg, 256>>>(x, 0, Wq, nullptr, 0, 0);  // -> g_q
    gemm_nt_kernel<<<gg, 256>>>(x, 0, Wk, nullptr, 1, 0);  // -> g_k
    gemm_nt_kernel<<<gg, 256>>>(x, 0, Wv, nullptr, 2, 1);  // -> g_v (SiLU)
    gemm_nt_kernel<<<gg, 256>>>(x, 0, Wg, nullptr, 3, 1);  // -> g_g (SiLU)
    ab_kernel<<<NROWS, 256>>>(x, Wa, ba, Wb, bb);
    l2norm_kernel<<<(NROWS*NH)/8, 256>>>(0);   // q
    l2norm_kernel<<<(NROWS*NH)/8, 256>>>(1);   // k
    pass1_kernel<<<dim3(NCHUNK, BHDIM), 512>>>();
    scan_kernel<<<BHDIM, 512>>>();
    pass2_kernel<<<dim3(NCHUNK, BHDIM), 512>>>();
    ln_gate_kernel<<<NROWS, 256>>>(lng, lnb);
    gemm_nt_kernel<<<gg, 256>>>(nullptr, 1, Wo, out, 4, 0); // g_attn -> out
}

// round 3
// speedup vs baseline: 1.4635x; 1.4635x over previous
#include <cuda_runtime.h>
#include <cuda_bf16.h>
#include <cstdint>

// Problem constants
#define BB 4
#define SS 2048
#define HH 1024
#define NH 16
#define HD 64
#define NROWS (BB*SS)          // 8192
#define CHUNK 64
#define NCHUNK (SS/CHUNK)      // 32
#define BHDIM (BB*NH)          // 64
#define SE (HD*HD)             // 4096

// ---------------- scratch (static __device__, allocation-free) ----------------
__device__ __align__(16) float g_q[(size_t)NROWS*HH];
__device__ __align__(16) float g_k[(size_t)NROWS*HH];
__device__ __align__(16) float g_v[(size_t)NROWS*HH];
__device__ __align__(16) float g_g[(size_t)NROWS*HH];
__device__ __align__(16) float g_attn[(size_t)NROWS*HH];
__device__ float g_alpha[NROWS*NH];
__device__ float g_beta[NROWS*NH];
__device__ __align__(16) float g_M [(size_t)BHDIM*NCHUNK*SE];
__device__ __align__(16) float g_Cc[(size_t)BHDIM*NCHUNK*SE];
__device__ __align__(16) float g_S0[(size_t)BHDIM*NCHUNK*SE];

// bf16 split buffers
__device__ __align__(16) __nv_bfloat16 g_xhi[(size_t)NROWS*HH];
__device__ __align__(16) __nv_bfloat16 g_xlo[(size_t)NROWS*HH];
__device__ __align__(16) __nv_bfloat16 g_whi[(size_t)5*HH*HH];
__device__ __align__(16) __nv_bfloat16 g_wlo[(size_t)5*HH*HH];
__device__ __align__(16) __nv_bfloat16 g_ahi[(size_t)NROWS*HH];
__device__ __align__(16) __nv_bfloat16 g_alo[(size_t)NROWS*HH];

__device__ __forceinline__ float sigmoidf_(float z){ return 1.f/(1.f+expf(-z)); }

// ---------------- fp32 -> bf16 hi/lo split ----------------------------------
__global__ void __launch_bounds__(256) cvt_kernel(const float* __restrict__ src,
                                                  int dsel, size_t off, int n4)
{
    const int i = blockIdx.x*256 + threadIdx.x;
    if (i >= n4) return;
    float4 v;
    if (dsel == 2) v = reinterpret_cast<const float4*>(g_attn)[i];
    else           v = reinterpret_cast<const float4*>(src)[i];
    __nv_bfloat16 *hi, *lo;
    if (dsel == 0){ hi = g_xhi; lo = g_xlo; }
    else if (dsel == 1){ hi = g_whi + off; lo = g_wlo + off; }
    else { hi = g_ahi; lo = g_alo; }
    float f[4] = {v.x, v.y, v.z, v.w};
    __nv_bfloat16 h[4], l[4];
    #pragma unroll
    for (int j=0;j<4;j++){
        h[j] = __float2bfloat16_rn(f[j]);
        l[j] = __float2bfloat16_rn(f[j] - __bfloat162float(h[j]));
    }
    __nv_bfloat162* hp = reinterpret_cast<__nv_bfloat162*>(hi + (size_t)4*i);
    __nv_bfloat162* lp = reinterpret_cast<__nv_bfloat162*>(lo + (size_t)4*i);
    hp[0] = __halves2bfloat162(h[0], h[1]);
    hp[1] = __halves2bfloat162(h[2], h[3]);
    lp[0] = __halves2bfloat162(l[0], l[1]);
    lp[1] = __halves2bfloat162(l[2], l[3]);
}

// ---------------- mma.sync bf16-split GEMM -----------------------------------
// C[M,N] = A[M,K] * W[N,K]^T with A=Ahi+Alo, W=Whi+Wlo (drop lo*lo).
// 128x128 tile, K-stage 32, double-buffered cp.async, 256 threads (8 warps,
// warp tile 64x32). Fragments loaded with lds.b32 (80B row pitch: conflict-free).
#define SROW 40                    // bf16 elems per smem row (80 B)
#define STG  (128*SROW)            // elems per matrix per stage (5120)
#define NKT  (HH/32)               // 32 K-stages
#define MM_SMEM (2*4*STG*2)        // bytes: 2 stages * 4 matrices * 5120 elems * 2B = 81920

__device__ __forceinline__ void cp16(uint32_t smem, const void* gptr){
    const unsigned long long g = (unsigned long long)__cvta_generic_to_global(gptr);
    asm volatile("cp.async.cg.shared.global [%0], [%1], 16;" :: "r"(smem), "l"(g) : "memory");
}

__device__ __forceinline__ void mma16816(float* c, const uint32_t* a, const uint32_t* b){
    asm volatile("mma.sync.aligned.m16n8k16.row.col.f32.bf16.bf16.f32 "
        "{%0,%1,%2,%3}, {%4,%5,%6,%7}, {%8,%9}, {%0,%1,%2,%3};"
        : "+f"(c[0]), "+f"(c[1]), "+f"(c[2]), "+f"(c[3])
        : "r"(a[0]), "r"(a[1]), "r"(a[2]), "r"(a[3]), "r"(b[0]), "r"(b[1]));
}

__global__ void __launch_bounds__(256) mm_kernel(int mode, float* __restrict__ Cext)
{
    extern __shared__ __align__(16) __nv_bfloat16 smem_bf[];
    const uint32_t sba = (uint32_t)__cvta_generic_to_shared(smem_bf);
    const int tid = threadIdx.x;
    const int wid = tid >> 5, lid = tid & 31;
    const int g = lid >> 2, tg = lid & 3;
    const int wm = wid & 1, wn = wid >> 1;     // 2 x 4 warp grid

    const int m0 = blockIdx.y * 128;
    const int n0 = blockIdx.x * 128;
    const int wrow = (mode ? 4096 : 0) + n0;
    const __nv_bfloat16* Ah = mode ? g_ahi : g_xhi;
    const __nv_bfloat16* Al = mode ? g_alo : g_xlo;

    float acc[4][4][4];
    #pragma unroll
    for (int a=0;a<4;a++)
        #pragma unroll
        for (int b=0;b<4;b++)
            #pragma unroll
            for (int c=0;c<4;c++) acc[a][b][c] = 0.f;

    // per-thread load coords (2 chunks of 16B per matrix per stage)
    const int ch0row = tid >> 2,            ch0c = (tid & 3);
    const int ch1row = (tid+256) >> 2,      ch1c = ((tid+256) & 3);

    auto load_stage = [&](int kt){
        const uint32_t sb2 = sba + (uint32_t)((kt & 1) * 4 * STG) * 2;
        const int k0 = kt * 32;
        {
            const int row = ch0row, c16 = ch0c;
            const uint32_t d = (uint32_t)(row*SROW + c16*8) * 2;
            const size_t ka = (size_t)k0 + c16*8;
            const size_t aoff = (size_t)(m0 + row)*HH + ka;
            const size_t boff = (size_t)(wrow + row)*HH + ka;
            cp16(sb2 + d,             Ah    + aoff);
            cp16(sb2 + STG*2 + d,     Al    + aoff);
            cp16(sb2 + 2*STG*2 + d,   g_whi + boff);
            cp16(sb2 + 3*STG*2 + d,   g_wlo + boff);
        }
        {
            const int row = ch1row, c16 = ch1c;
            const uint32_t d = (uint32_t)(row*SROW + c16*8) * 2;
            const size_t ka = (size_t)k0 + c16*8;
            const size_t aoff = (size_t)(m0 + row)*HH + ka;
            const size_t boff = (size_t)(wrow + row)*HH + ka;
            cp16(sb2 + d,             Ah    + aoff);
            cp16(sb2 + STG*2 + d,     Al    + aoff);
            cp16(sb2 + 2*STG*2 + d,   g_whi + boff);
            cp16(sb2 + 3*STG*2 + d,   g_wlo + boff);
        }
        asm volatile("cp.async.commit_group;" ::: "memory");
    };

    load_stage(0);

    for (int kt = 0; kt < NKT; ++kt){
        if (kt + 1 < NKT) load_stage(kt + 1);
        if (kt + 1 < NKT) asm volatile("cp.async.wait_group 1;" ::: "memory");
        else              asm volatile("cp.async.wait_group 0;" ::: "memory");
        __syncthreads();

        const int sb = (kt & 1) * 4 * STG;
        #pragma unroll
        for (int ks = 0; ks < 2; ++ks){
            const int c0 = ks*16 + 2*tg;
            // B fragments (hi + lo)
            uint32_t bh[4][2], bl[4][2];
            #pragma unroll
            for (int nt = 0; nt < 4; ++nt){
                const int rn = wn*32 + nt*8 + g;
                const __nv_bfloat16* wh = smem_bf + sb + 2*STG + rn*SROW;
                const __nv_bfloat16* wl = smem_bf + sb + 3*STG + rn*SROW;
                bh[nt][0] = *reinterpret_cast<const uint32_t*>(wh + c0);
                bh[nt][1] = *reinterpret_cast<const uint32_t*>(wh + c0 + 8);
                bl[nt][0] = *reinterpret_cast<const uint32_t*>(wl + c0);
                bl[nt][1] = *reinterpret_cast<const uint32_t*>(wl + c0 + 8);
            }
            #pragma unroll
            for (int mt = 0; mt < 4; ++mt){
                const int rm = wm*64 + mt*16 + g;
                const __nv_bfloat16* ah = smem_bf + sb + rm*SROW;
                uint32_t af[4];
                af[0] = *reinterpret_cast<const uint32_t*>(ah + c0);
                af[1] = *reinterpret_cast<const uint32_t*>(ah + 8*SROW + c0);
                af[2] = *reinterpret_cast<const uint32_t*>(ah + c0 + 8);
                af[3] = *reinterpret_cast<const uint32_t*>(ah + 8*SROW + c0 + 8);
                #pragma unroll
                for (int nt = 0; nt < 4; ++nt){
                    mma16816(acc[mt][nt], af, bh[nt]);
                    mma16816(acc[mt][nt], af, bl[nt]);
                }
                const __nv_bfloat16* al = smem_bf + sb + STG + rm*SROW;
                af[0] = *reinterpret_cast<const uint32_t*>(al + c0);
                af[1] = *reinterpret_cast<const uint32_t*>(al + 8*SROW + c0);
                af[2] = *reinterpret_cast<const uint32_t*>(al + c0 + 8);
                af[3] = *reinterpret_cast<const uint32_t*>(al + 8*SROW + c0 + 8);
                #pragma unroll
                for (int nt = 0; nt < 4; ++nt)
                    mma16816(acc[mt][nt], af, bh[nt]);
            }
        }
        __syncthreads();
    }

    // epilogue
    float* dst; int epi = 0; int colb;
    if (mode == 0){
        const int mat = n0 >> 10;
        colb = n0 & 1023;
        switch (mat){
            case 0: dst = g_q; break;
            case 1: dst = g_k; break;
            case 2: dst = g_v; epi = 1; break;
            default: dst = g_g; epi = 1; break;
        }
    } else { dst = Cext; colb = n0; }

    #pragma unroll
    for (int mt = 0; mt < 4; ++mt){
        const int r = m0 + wm*64 + mt*16 + g;
        #pragma unroll
        for (int nt = 0; nt < 4; ++nt){
            const int cidx = colb + wn*32 + nt*8 + 2*tg;
            float v0 = acc[mt][nt][0], v1 = acc[mt][nt][1];
            float v2 = acc[mt][nt][2], v3 = acc[mt][nt][3];
            if (epi){
                v0 *= sigmoidf_(v0); v1 *= sigmoidf_(v1);
                v2 *= sigmoidf_(v2); v3 *= sigmoidf_(v3);
            }
            *reinterpret_cast<float2*>(dst + (size_t)r*HH + cidx)     = make_float2(v0, v1);
            *reinterpret_cast<float2*>(dst + (size_t)(r+8)*HH + cidx) = make_float2(v2, v3);
        }
    }
}

// ---------------- alpha/beta: sigmoid(x @ [Wa;Wb]^T + bias) ------------------
__global__ void __launch_bounds__(256) ab_kernel(
    const float* __restrict__ x,
    const float* __restrict__ Wa, const float* __restrict__ ba,
    const float* __restrict__ Wb, const float* __restrict__ bb)
{
    __shared__ float xs[HH];
    __shared__ float part[32][9];
    const int r = blockIdx.x, tid = threadIdx.x;
    for (int i=tid;i<HH;i+=256) xs[i] = x[(size_t)r*HH + i];
    __syncthreads();
    const int o = tid >> 3, sl = tid & 7;
    const float* wrow = (o < NH) ? (Wa + (size_t)o*HH) : (Wb + (size_t)(o-NH)*HH);
    float p = 0.f;
    const int k0 = sl * 128;
    #pragma unroll 8
    for (int kk=0; kk<128; ++kk) p = fmaf(xs[k0+kk], wrow[k0+kk], p);
    part[o][sl] = p;
    __syncthreads();
    if (tid < 32){
        float s = 0.f;
        #pragma unroll
        for (int j=0;j<8;j++) s += part[tid][j];
        s += (tid < NH) ? ba[tid] : bb[tid-NH];
        s = sigmoidf_(s);
        if (tid < NH) g_alpha[r*NH + tid] = s;
        else          g_beta [r*NH + tid - NH] = s;
    }
}

// ---------------- per-head L2 normalization (in place) -----------------------
__global__ void __launch_bounds__(256) l2norm_kernel(int sel)
{
    float* base = sel ? g_k : g_q;
    const int gw = (blockIdx.x*blockDim.x + threadIdx.x) >> 5;
    const int l = threadIdx.x & 31;
    if (gw >= NROWS*NH) return;
    float* v = base + (size_t)gw * HD;
    float a = v[l], b = v[l+32];
    float ss = fmaf(a, a, b*b);
    #pragma unroll
    for (int o=16;o;o>>=1) ss += __shfl_xor_sync(0xffffffffu, ss, o);
    const float inv = 1.f / fmaxf(sqrtf(ss), 1e-12f);
    v[l]    = a * inv;
    v[l+32] = b * inv;
}

// ---------------- recurrence pass 1: per-chunk transitions -------------------
__global__ void __launch_bounds__(512) pass1_kernel()
{
    const int c = blockIdx.x, bh = blockIdx.y;
    const int b = bh >> 4, h = bh & 15;
    const int tid = threadIdx.x;
    const int w = tid >> 5, l = tid & 31;
    __shared__ float ks[HD], vs[HD], sab[2];
    float M[4][2], Cc[4][2];
    #pragma unroll
    for (int r=0;r<4;r++){ M[r][0]=1.f; M[r][1]=1.f; Cc[r][0]=0.f; Cc[r][1]=0.f; }
    const int row0 = b*SS + c*CHUNK;
    for (int t=0;t<CHUNK;++t){
        const int row = row0 + t;
        __syncthreads();
        if (tid < 64)        ks[tid]     = g_k[(size_t)row*HH + h*HD + tid];
        else if (tid < 128)  vs[tid-64]  = g_v[(size_t)row*HH + h*HD + (tid-64)];
        else if (tid == 128) sab[0] = g_alpha[row*NH + h];
        else if (tid == 129) sab[1] = g_beta [row*NH + h];
        __syncthreads();
        const float a = sab[0], bt = sab[1], abp = a*bt;
        const float kj0 = ks[l], kj1 = ks[l+32];
        #pragma unroll
        for (int r=0;r<4;r++){
            const int i = w*4 + r;
            const float ki = ks[i];
            const float bvi = bt * vs[i];
            const float abki = abp * ki;
            const float m0 = fmaf(-abki, kj0, a);
            const float m1 = fmaf(-abki, kj1, a);
            M[r][0] *= m0;  M[r][1] *= m1;
            Cc[r][0] = fmaf(m0, Cc[r][0], bvi*kj0);
            Cc[r][1] = fmaf(m1, Cc[r][1], bvi*kj1);
        }
    }
    const size_t ob = ((size_t)bh*NCHUNK + c) * SE;
    #pragma unroll
    for (int r=0;r<4;r++){
        const int i = w*4 + r;
        g_M [ob + i*HD + l]      = M[r][0];
        g_M [ob + i*HD + l + 32] = M[r][1];
        g_Cc[ob + i*HD + l]      = Cc[r][0];
        g_Cc[ob + i*HD + l + 32] = Cc[r][1];
    }
}

// ---------------- serial scan over chunks ------------------------------------
__global__ void __launch_bounds__(512) scan_kernel()
{
    const int bh = blockIdx.x;
    const size_t base = (size_t)bh * NCHUNK * SE;
    float s[8];
    #pragma unroll
    for (int u=0;u<8;u++) s[u] = 0.f;
    for (int c=0;c<NCHUNK;++c){
        const size_t cb = base + (size_t)c*SE + threadIdx.x;
        #pragma unroll
        for (int u=0;u<8;u++){
            const size_t idx = cb + (size_t)u*512;
            g_S0[idx] = s[u];
            s[u] = fmaf(g_M[idx], s[u], g_Cc[idx]);
        }
    }
}

// ---------------- recurrence pass 2 ------------------------------------------
__global__ void __launch_bounds__(512) pass2_kernel()
{
    const int c = blockIdx.x, bh = blockIdx.y;
    const int b = bh >> 4, h = bh & 15;
    const int tid = threadIdx.x;
    const int w = tid >> 5, l = tid & 31;
    __shared__ float ks[HD], vs[HD], qs[HD], sab[2];
    float st[4][2];
    const size_t sbg = ((size_t)bh*NCHUNK + c) * SE;
    #pragma unroll
    for (int r=0;r<4;r++){
        const int i = w*4 + r;
        st[r][0] = g_S0[sbg + i*HD + l];
        st[r][1] = g_S0[sbg + i*HD + l + 32];
    }
    const int row0 = b*SS + c*CHUNK;
    for (int t=0;t<CHUNK;++t){
        const int row = row0 + t;
        __syncthreads();
        if (tid < 64)        ks[tid]      = g_k[(size_t)row*HH + h*HD + tid];
        else if (tid < 128)  vs[tid-64]   = g_v[(size_t)row*HH + h*HD + (tid-64)];
        else if (tid < 192)  qs[tid-128]  = g_q[(size_t)row*HH + h*HD + (tid-128)];
        else if (tid == 192) sab[0] = g_alpha[row*NH + h];
        else if (tid == 193) sab[1] = g_beta [row*NH + h];
        __syncthreads();
        const float a = sab[0], bt = sab[1], abp = a*bt;
        const float kj0 = ks[l], kj1 = ks[l+32];
        const float qj0 = qs[l], qj1 = qs[l+32];
        float p[4];
        #pragma unroll
        for (int r=0;r<4;r++){
            const int i = w*4 + r;
            const float ki = ks[i];
            const float bvi = bt * vs[i];
            const float abki = abp * ki;
            const float m0 = fmaf(-abki, kj0, a);
            const float m1 = fmaf(-abki, kj1, a);
            st[r][0] = fmaf(m0, st[r][0], bvi*kj0);
            st[r][1] = fmaf(m1, st[r][1], bvi*kj1);
            p[r] = fmaf(st[r][0], qj0, st[r][1]*qj1);
        }
        #pragma unroll
        for (int o=16;o;o>>=1){
            p[0] += __shfl_xor_sync(0xffffffffu, p[0], o);
            p[1] += __shfl_xor_sync(0xffffffffu, p[1], o);
            p[2] += __shfl_xor_sync(0xffffffffu, p[2], o);
            p[3] += __shfl_xor_sync(0xffffffffu, p[3], o);
        }
        if (l < 4) g_attn[(size_t)row*HH + h*HD + w*4 + l] = p[l];
    }
}

// ---------------- LayerNorm + SiLU-gate (in place on g_attn) -----------------
__global__ void __launch_bounds__(256) ln_gate_kernel(
    const float* __restrict__ lng, const float* __restrict__ lnb)
{
    const int r = blockIdx.x, tid = threadIdx.x;
    __shared__ float xs[HH];
    __shared__ float red[8];
    float* row = g_attn + (size_t)r*HH;
    float s = 0.f;
    for (int i=tid;i<HH;i+=256){ float v = row[i]; xs[i] = v; s += v; }
    #pragma unroll
    for (int o=16;o;o>>=1) s += __shfl_xor_sync(0xffffffffu, s, o);
    if ((tid & 31) == 0) red[tid>>5] = s;
    __syncthreads();
    float tot = red[0]+red[1]+red[2]+red[3]+red[4]+red[5]+red[6]+red[7];
    const float mu = tot * (1.f/HH);
    __syncthreads();
    float vsum = 0.f;
    for (int i=tid;i<HH;i+=256){ float d = xs[i]-mu; vsum = fmaf(d,d,vsum); }
    #pragma unroll
    for (int o=16;o;o>>=1) vsum += __shfl_xor_sync(0xffffffffu, vsum, o);
    if ((tid & 31) == 0) red[tid>>5] = vsum;
    __syncthreads();
    float vtot = red[0]+red[1]+red[2]+red[3]+red[4]+red[5]+red[6]+red[7];
    const float rstd = rsqrtf(vtot*(1.f/HH) + 1e-5f);
    for (int i=tid;i<HH;i+=256){
        const float y = (xs[i]-mu)*rstd*lng[i] + lnb[i];
        row[i] = y * g_g[(size_t)r*HH + i];
    }
}

// ---------------- launch -----------------------------------------------------
extern "C" void kernel_launch(void* const* d_in, const int* in_sizes, int n_in,
                              void* d_out, int out_size)
{
    const float* x   = (const float*)d_in[0];
    const float* Wq  = (const float*)d_in[1];
    const float* Wk  = (const float*)d_in[2];
    const float* Wv  = (const float*)d_in[3];
    const float* Wa  = (const float*)d_in[4];
    const float* ba  = (const float*)d_in[5];
    const float* Wb  = (const float*)d_in[6];
    const float* bb  = (const float*)d_in[7];
    const float* Wg  = (const float*)d_in[8];
    const float* Wo  = (const float*)d_in[9];
    const float* lng = (const float*)d_in[10];
    const float* lnb = (const float*)d_in[11];
    float* out = (float*)d_out;

    cudaFuncSetAttribute(mm_kernel, cudaFuncAttributeMaxDynamicSharedMemorySize, MM_SMEM);

    const int XN4 = (NROWS*HH)/4;       // 2097152
    const int WN4 = (HH*HH)/4;          // 262144
    cvt_kernel<<<(XN4+255)/256, 256>>>(x,  0, 0, XN4);
    cvt_kernel<<<(WN4+255)/256, 256>>>(Wq, 1, (size_t)0*HH*HH, WN4);
    cvt_kernel<<<(WN4+255)/256, 256>>>(Wk, 1, (size_t)1*HH*HH, WN4);
    cvt_kernel<<<(WN4+255)/256, 256>>>(Wv, 1, (size_t)2*HH*HH, WN4);
    cvt_kernel<<<(WN4+255)/256, 256>>>(Wg, 1, (size_t)3*HH*HH, WN4);
    cvt_kernel<<<(WN4+255)/256, 256>>>(Wo, 1, (size_t)4*HH*HH, WN4);

    // fused Q|K|V|G GEMM on tensor cores (mma.sync bf16 split)
    mm_kernel<<<dim3(32, 64), 256, MM_SMEM>>>(0, nullptr);

    ab_kernel<<<NROWS, 256>>>(x, Wa, ba, Wb, bb);
    l2norm_kernel<<<(NROWS*NH)/8, 256>>>(0);
    l2norm_kernel<<<(NROWS*NH)/8, 256>>>(1);
    pass1_kernel<<<dim3(NCHUNK, BHDIM), 512>>>();
    scan_kernel<<<BHDIM, 512>>>();
    pass2_kernel<<<dim3(NCHUNK, BHDIM), 512>>>();
    ln_gate_kernel<<<NROWS, 256>>>(lng, lnb);

    cvt_kernel<<<(XN4+255)/256, 256>>>(nullptr, 2, 0, XN4);
    mm_kernel<<<dim3(8, 64), 256, MM_SMEM>>>(1, out);
}

// round 4
// speedup vs baseline: 1.7427x; 1.1908x over previous
#include <cuda_runtime.h>
#include <cuda_bf16.h>
#include <cstdint>

// Problem constants
#define BB 4
#define SS 2048
#define HH 1024
#define NH 16
#define HD 64
#define NROWS (BB*SS)          // 8192
#define CHUNK 64
#define NCHUNK (SS/CHUNK)      // 32
#define BHDIM (BB*NH)          // 64
#define SE (HD*HD)             // 4096

// ---------------- scratch (static __device__, allocation-free) ----------------
__device__ __align__(16) float g_q[(size_t)NROWS*HH];
__device__ __align__(16) float g_k[(size_t)NROWS*HH];
__device__ __align__(16) float g_v[(size_t)NROWS*HH];
__device__ __align__(16) float g_g[(size_t)NROWS*HH];
__device__ __align__(16) float g_attn[(size_t)NROWS*HH];
__device__ float g_alpha[NROWS*NH];
__device__ float g_beta[NROWS*NH];
__device__ __align__(16) float g_M [(size_t)BHDIM*NCHUNK*SE];
__device__ __align__(16) float g_Cc[(size_t)BHDIM*NCHUNK*SE];
__device__ __align__(16) float g_S0[(size_t)BHDIM*NCHUNK*SE];

// bf16 split buffers
__device__ __align__(16) __nv_bfloat16 g_xhi[(size_t)NROWS*HH];
__device__ __align__(16) __nv_bfloat16 g_xlo[(size_t)NROWS*HH];
__device__ __align__(16) __nv_bfloat16 g_whi[(size_t)5*HH*HH];
__device__ __align__(16) __nv_bfloat16 g_wlo[(size_t)5*HH*HH];
__device__ __align__(16) __nv_bfloat16 g_ahi[(size_t)NROWS*HH];
__device__ __align__(16) __nv_bfloat16 g_alo[(size_t)NROWS*HH];

__device__ __forceinline__ float sigmoidf_(float z){ return 1.f/(1.f+expf(-z)); }

__device__ __forceinline__ void split4(float4 v, __nv_bfloat16* hi, __nv_bfloat16* lo){
    float f[4] = {v.x, v.y, v.z, v.w};
    __nv_bfloat16 h[4], l[4];
    #pragma unroll
    for (int j=0;j<4;j++){
        h[j] = __float2bfloat16_rn(f[j]);
        l[j] = __float2bfloat16_rn(f[j] - __bfloat162float(h[j]));
    }
    reinterpret_cast<__nv_bfloat162*>(hi)[0] = __halves2bfloat162(h[0], h[1]);
    reinterpret_cast<__nv_bfloat162*>(hi)[1] = __halves2bfloat162(h[2], h[3]);
    reinterpret_cast<__nv_bfloat162*>(lo)[0] = __halves2bfloat162(l[0], l[1]);
    reinterpret_cast<__nv_bfloat162*>(lo)[1] = __halves2bfloat162(l[2], l[3]);
}

// ---------------- fp32 -> bf16 hi/lo split: x ---------------------------------
__global__ void __launch_bounds__(256) cvt_x_kernel(const float* __restrict__ src)
{
    const int i = blockIdx.x*256 + threadIdx.x;
    if (i >= (NROWS*HH)/4) return;
    split4(reinterpret_cast<const float4*>(src)[i], g_xhi + 4*(size_t)i, g_xlo + 4*(size_t)i);
}

// ---------------- fp32 -> bf16 hi/lo split: 5 weights --------------------------
__global__ void __launch_bounds__(256) cvt_w_kernel(
    const float* __restrict__ W0, const float* __restrict__ W1,
    const float* __restrict__ W2, const float* __restrict__ W3,
    const float* __restrict__ W4)
{
    const int WN4 = (HH*HH)/4;
    const int i = blockIdx.x*256 + threadIdx.x;
    if (i >= 5*WN4) return;
    const int mat = i / WN4, j = i - mat*WN4;
    const float* src;
    switch (mat){
        case 0: src = W0; break; case 1: src = W1; break;
        case 2: src = W2; break; case 3: src = W3; break;
        default: src = W4; break;
    }
    const size_t o = (size_t)mat*HH*HH + 4*(size_t)j;
    split4(reinterpret_cast<const float4*>(src)[j], g_whi + o, g_wlo + o);
}

// ---------------- mma.sync bf16-split GEMM -----------------------------------
#define SROW 40
#define STG  (128*SROW)
#define NKT  (HH/32)
#define MM_SMEM (2*4*STG*2)

__device__ __forceinline__ void cp16(uint32_t smem, const void* gptr){
    const unsigned long long g = (unsigned long long)__cvta_generic_to_global(gptr);
    asm volatile("cp.async.cg.shared.global [%0], [%1], 16;" :: "r"(smem), "l"(g) : "memory");
}

__device__ __forceinline__ void mma16816(float* c, const uint32_t* a, const uint32_t* b){
    asm volatile("mma.sync.aligned.m16n8k16.row.col.f32.bf16.bf16.f32 "
        "{%0,%1,%2,%3}, {%4,%5,%6,%7}, {%8,%9}, {%0,%1,%2,%3};"
        : "+f"(c[0]), "+f"(c[1]), "+f"(c[2]), "+f"(c[3])
        : "r"(a[0]), "r"(a[1]), "r"(a[2]), "r"(a[3]), "r"(b[0]), "r"(b[1]));
}

__global__ void __launch_bounds__(256) mm_kernel(int mode, float* __restrict__ Cext)
{
    extern __shared__ __align__(16) __nv_bfloat16 smem_bf[];
    const uint32_t sba = (uint32_t)__cvta_generic_to_shared(smem_bf);
    const int tid = threadIdx.x;
    const int wid = tid >> 5, lid = tid & 31;
    const int g = lid >> 2, tg = lid & 3;
    const int wm = wid & 1, wn = wid >> 1;

    const int m0 = blockIdx.y * 128;
    const int n0 = blockIdx.x * 128;
    const int wrow = (mode ? 4096 : 0) + n0;
    const __nv_bfloat16* Ah = mode ? g_ahi : g_xhi;
    const __nv_bfloat16* Al = mode ? g_alo : g_xlo;

    float acc[4][4][4];
    #pragma unroll
    for (int a=0;a<4;a++)
        #pragma unroll
        for (int b=0;b<4;b++)
            #pragma unroll
            for (int c=0;c<4;c++) acc[a][b][c] = 0.f;

    const int ch0row = tid >> 2,        ch0c = (tid & 3);
    const int ch1row = (tid+256) >> 2,  ch1c = ((tid+256) & 3);

    auto load_stage = [&](int kt){
        const uint32_t sb2 = sba + (uint32_t)((kt & 1) * 4 * STG) * 2;
        const int k0 = kt * 32;
        {
            const int row = ch0row, c16 = ch0c;
            const uint32_t d = (uint32_t)(row*SROW + c16*8) * 2;
            const size_t ka = (size_t)k0 + c16*8;
            const size_t aoff = (size_t)(m0 + row)*HH + ka;
            const size_t boff = (size_t)(wrow + row)*HH + ka;
            cp16(sb2 + d,             Ah    + aoff);
            cp16(sb2 + STG*2 + d,     Al    + aoff);
            cp16(sb2 + 2*STG*2 + d,   g_whi + boff);
            cp16(sb2 + 3*STG*2 + d,   g_wlo + boff);
        }
        {
            const int row = ch1row, c16 = ch1c;
            const uint32_t d = (uint32_t)(row*SROW + c16*8) * 2;
            const size_t ka = (size_t)k0 + c16*8;
            const size_t aoff = (size_t)(m0 + row)*HH + ka;
            const size_t boff = (size_t)(wrow + row)*HH + ka;
            cp16(sb2 + d,             Ah    + aoff);
            cp16(sb2 + STG*2 + d,     Al    + aoff);
            cp16(sb2 + 2*STG*2 + d,   g_whi + boff);
            cp16(sb2 + 3*STG*2 + d,   g_wlo + boff);
        }
        asm volatile("cp.async.commit_group;" ::: "memory");
    };

    load_stage(0);

    for (int kt = 0; kt < NKT; ++kt){
        if (kt + 1 < NKT) load_stage(kt + 1);
        if (kt + 1 < NKT) asm volatile("cp.async.wait_group 1;" ::: "memory");
        else              asm volatile("cp.async.wait_group 0;" ::: "memory");
        __syncthreads();

        const int sb = (kt & 1) * 4 * STG;
        #pragma unroll
        for (int ks = 0; ks < 2; ++ks){
            const int c0 = ks*16 + 2*tg;
            uint32_t bh[4][2], bl[4][2];
            #pragma unroll
            for (int nt = 0; nt < 4; ++nt){
                const int rn = wn*32 + nt*8 + g;
                const __nv_bfloat16* wh = smem_bf + sb + 2*STG + rn*SROW;
                const __nv_bfloat16* wl = smem_bf + sb + 3*STG + rn*SROW;
                bh[nt][0] = *reinterpret_cast<const uint32_t*>(wh + c0);
                bh[nt][1] = *reinterpret_cast<const uint32_t*>(wh + c0 + 8);
                bl[nt][0] = *reinterpret_cast<const uint32_t*>(wl + c0);
                bl[nt][1] = *reinterpret_cast<const uint32_t*>(wl + c0 + 8);
            }
            #pragma unroll
            for (int mt = 0; mt < 4; ++mt){
                const int rm = wm*64 + mt*16 + g;
                const __nv_bfloat16* ah = smem_bf + sb + rm*SROW;
                uint32_t af[4];
                af[0] = *reinterpret_cast<const uint32_t*>(ah + c0);
                af[1] = *reinterpret_cast<const uint32_t*>(ah + 8*SROW + c0);
                af[2] = *reinterpret_cast<const uint32_t*>(ah + c0 + 8);
                af[3] = *reinterpret_cast<const uint32_t*>(ah + 8*SROW + c0 + 8);
                #pragma unroll
                for (int nt = 0; nt < 4; ++nt){
                    mma16816(acc[mt][nt], af, bh[nt]);
                    mma16816(acc[mt][nt], af, bl[nt]);
                }
                const __nv_bfloat16* al = smem_bf + sb + STG + rm*SROW;
                af[0] = *reinterpret_cast<const uint32_t*>(al + c0);
                af[1] = *reinterpret_cast<const uint32_t*>(al + 8*SROW + c0);
                af[2] = *reinterpret_cast<const uint32_t*>(al + c0 + 8);
                af[3] = *reinterpret_cast<const uint32_t*>(al + 8*SROW + c0 + 8);
                #pragma unroll
                for (int nt = 0; nt < 4; ++nt)
                    mma16816(acc[mt][nt], af, bh[nt]);
            }
        }
        __syncthreads();
    }

    float* dst; int epi = 0; int colb;
    if (mode == 0){
        const int mat = n0 >> 10;
        colb = n0 & 1023;
        switch (mat){
            case 0: dst = g_q; break;
            case 1: dst = g_k; break;
            case 2: dst = g_v; epi = 1; break;
            default: dst = g_g; epi = 1; break;
        }
    } else { dst = Cext; colb = n0; }

    #pragma unroll
    for (int mt = 0; mt < 4; ++mt){
        const int r = m0 + wm*64 + mt*16 + g;
        #pragma unroll
        for (int nt = 0; nt < 4; ++nt){
            const int cidx = colb + wn*32 + nt*8 + 2*tg;
            float v0 = acc[mt][nt][0], v1 = acc[mt][nt][1];
            float v2 = acc[mt][nt][2], v3 = acc[mt][nt][3];
            if (epi){
                v0 *= sigmoidf_(v0); v1 *= sigmoidf_(v1);
                v2 *= sigmoidf_(v2); v3 *= sigmoidf_(v3);
            }
            *reinterpret_cast<float2*>(dst + (size_t)r*HH + cidx)     = make_float2(v0, v1);
            *reinterpret_cast<float2*>(dst + (size_t)(r+8)*HH + cidx) = make_float2(v2, v3);
        }
    }
}

// ---------------- alpha/beta: sigmoid(x @ [Wa;Wb]^T + bias) ------------------
__global__ void __launch_bounds__(256) ab_kernel(
    const float* __restrict__ x,
    const float* __restrict__ Wa, const float* __restrict__ ba,
    const float* __restrict__ Wb, const float* __restrict__ bb)
{
    __shared__ float xs[HH];
    __shared__ float part[32][9];
    const int r = blockIdx.x, tid = threadIdx.x;
    for (int i=tid;i<HH;i+=256) xs[i] = x[(size_t)r*HH + i];
    __syncthreads();
    const int o = tid >> 3, sl = tid & 7;
    const float* wrow = (o < NH) ? (Wa + (size_t)o*HH) : (Wb + (size_t)(o-NH)*HH);
    float p = 0.f;
    const int k0 = sl * 128;
    #pragma unroll 8
    for (int kk=0; kk<128; ++kk) p = fmaf(xs[k0+kk], wrow[k0+kk], p);
    part[o][sl] = p;
    __syncthreads();
    if (tid < 32){
        float s = 0.f;
        #pragma unroll
        for (int j=0;j<8;j++) s += part[tid][j];
        s += (tid < NH) ? ba[tid] : bb[tid-NH];
        s = sigmoidf_(s);
        if (tid < NH) g_alpha[r*NH + tid] = s;
        else          g_beta [r*NH + tid - NH] = s;
    }
}

// ---------------- per-head L2 normalization (q then k, one launch) -----------
__global__ void __launch_bounds__(256) l2qk_kernel()
{
    const int gw = (blockIdx.x*blockDim.x + threadIdx.x) >> 5;
    const int l = threadIdx.x & 31;
    const int tot = NROWS*NH;
    if (gw >= 2*tot) return;
    float* v = (gw < tot) ? (g_q + (size_t)gw*HD) : (g_k + (size_t)(gw-tot)*HD);
    float a = v[l], b = v[l+32];
    float ss = fmaf(a, a, b*b);
    #pragma unroll
    for (int o=16;o;o>>=1) ss += __shfl_xor_sync(0xffffffffu, ss, o);
    const float inv = 1.f / fmaxf(sqrtf(ss), 1e-12f);
    v[l]    = a * inv;
    v[l+32] = b * inv;
}

// ---------------- recurrence pass 1: chunk-preloaded, barrier-free loop ------
__global__ void __launch_bounds__(512) pass1_kernel()
{
    const int c = blockIdx.x, bh = blockIdx.y;
    const int b = bh >> 4, h = bh & 15;
    const int tid = threadIdx.x;
    const int w = tid >> 5, l = tid & 31;
    __shared__ __align__(16) float ks[CHUNK*HD];
    __shared__ __align__(16) float vs[CHUNK*HD];
    __shared__ float aa[CHUNK], bbs[CHUNK];

    const int row0 = b*SS + c*CHUNK;
    for (int idx = tid; idx < CHUNK*16; idx += 512){
        const int t = idx >> 4, c4 = (idx & 15) * 4;
        const size_t go = (size_t)(row0 + t)*HH + h*HD + c4;
        *reinterpret_cast<float4*>(&ks[t*HD + c4]) = *reinterpret_cast<const float4*>(&g_k[go]);
        *reinterpret_cast<float4*>(&vs[t*HD + c4]) = *reinterpret_cast<const float4*>(&g_v[go]);
    }
    if (tid < CHUNK){
        aa[tid]  = g_alpha[(row0 + tid)*NH + h];
        bbs[tid] = g_beta [(row0 + tid)*NH + h];
    }
    __syncthreads();

    float M[4][2], Cc[4][2];
    #pragma unroll
    for (int r=0;r<4;r++){ M[r][0]=1.f; M[r][1]=1.f; Cc[r][0]=0.f; Cc[r][1]=0.f; }

    for (int t=0;t<CHUNK;++t){
        const float a = aa[t], bt = bbs[t], abp = a*bt;
        const float kj0 = ks[t*HD + l], kj1 = ks[t*HD + l + 32];
        #pragma unroll
        for (int r=0;r<4;r++){
            const int i = w*4 + r;
            const float ki = ks[t*HD + i];
            const float bvi = bt * vs[t*HD + i];
            const float abki = abp * ki;
            const float m0 = fmaf(-abki, kj0, a);
            const float m1 = fmaf(-abki, kj1, a);
            M[r][0] *= m0;  M[r][1] *= m1;
            Cc[r][0] = fmaf(m0, Cc[r][0], bvi*kj0);
            Cc[r][1] = fmaf(m1, Cc[r][1], bvi*kj1);
        }
    }
    const size_t ob = ((size_t)bh*NCHUNK + c) * SE;
    #pragma unroll
    for (int r=0;r<4;r++){
        const int i = w*4 + r;
        g_M [ob + i*HD + l]      = M[r][0];
        g_M [ob + i*HD + l + 32] = M[r][1];
        g_Cc[ob + i*HD + l]      = Cc[r][0];
        g_Cc[ob + i*HD + l + 32] = Cc[r][1];
    }
}

// ---------------- serial scan over chunks ------------------------------------
__global__ void __launch_bounds__(512) scan_kernel()
{
    const int bh = blockIdx.x;
    const size_t base = (size_t)bh * NCHUNK * SE;
    float s[8];
    #pragma unroll
    for (int u=0;u<8;u++) s[u] = 0.f;
    for (int c=0;c<NCHUNK;++c){
        const size_t cb = base + (size_t)c*SE + threadIdx.x;
        #pragma unroll
        for (int u=0;u<8;u++){
            const size_t idx = cb + (size_t)u*512;
            g_S0[idx] = s[u];
            s[u] = fmaf(g_M[idx], s[u], g_Cc[idx]);
        }
    }
}

// ---------------- recurrence pass 2: chunk-preloaded + staged output ---------
#define P2_SMEM (4*CHUNK*HD*4 + 2*CHUNK*4)   // k,v,q,out + a,b = 66048 B
__global__ void __launch_bounds__(512) pass2_kernel()
{
    const int c = blockIdx.x, bh = blockIdx.y;
    const int b = bh >> 4, h = bh & 15;
    const int tid = threadIdx.x;
    const int w = tid >> 5, l = tid & 31;
    extern __shared__ __align__(16) float p2s[];
    float* ks  = p2s;
    float* vs  = p2s + CHUNK*HD;
    float* qs  = p2s + 2*CHUNK*HD;
    float* outs= p2s + 3*CHUNK*HD;
    float* aa  = p2s + 4*CHUNK*HD;
    float* bbs = aa + CHUNK;

    const int row0 = b*SS + c*CHUNK;
    for (int idx = tid; idx < CHUNK*16; idx += 512){
        const int t = idx >> 4, c4 = (idx & 15) * 4;
        const size_t go = (size_t)(row0 + t)*HH + h*HD + c4;
        *reinterpret_cast<float4*>(&ks[t*HD + c4]) = *reinterpret_cast<const float4*>(&g_k[go]);
        *reinterpret_cast<float4*>(&vs[t*HD + c4]) = *reinterpret_cast<const float4*>(&g_v[go]);
        *reinterpret_cast<float4*>(&qs[t*HD + c4]) = *reinterpret_cast<const float4*>(&g_q[go]);
    }
    if (tid < CHUNK){
        aa[tid]  = g_alpha[(row0 + tid)*NH + h];
        bbs[tid] = g_beta [(row0 + tid)*NH + h];
    }

    float st[4][2];
    const size_t sbg = ((size_t)bh*NCHUNK + c) * SE;
    #pragma unroll
    for (int r=0;r<4;r++){
        const int i = w*4 + r;
        st[r][0] = g_S0[sbg + i*HD + l];
        st[r][1] = g_S0[sbg + i*HD + l + 32];
    }
    __syncthreads();

    for (int t=0;t<CHUNK;++t){
        const float a = aa[t], bt = bbs[t], abp = a*bt;
        const float kj0 = ks[t*HD + l], kj1 = ks[t*HD + l + 32];
        const float qj0 = qs[t*HD + l], qj1 = qs[t*HD + l + 32];
        float p[4];
        #pragma unroll
        for (int r=0;r<4;r++){
            const int i = w*4 + r;
            const float ki = ks[t*HD + i];
            const float bvi = bt * vs[t*HD + i];
            const float abki = abp * ki;
            const float m0 = fmaf(-abki, kj0, a);
            const float m1 = fmaf(-abki, kj1, a);
            st[r][0] = fmaf(m0, st[r][0], bvi*kj0);
            st[r][1] = fmaf(m1, st[r][1], bvi*kj1);
            p[r] = fmaf(st[r][0], qj0, st[r][1]*qj1);
        }
        #pragma unroll
        for (int o=16;o;o>>=1){
            p[0] += __shfl_xor_sync(0xffffffffu, p[0], o);
            p[1] += __shfl_xor_sync(0xffffffffu, p[1], o);
            p[2] += __shfl_xor_sync(0xffffffffu, p[2], o);
            p[3] += __shfl_xor_sync(0xffffffffu, p[3], o);
        }
        if (l < 4) outs[t*HD + w*4 + l] = p[l];
    }
    __syncthreads();
    for (int idx = tid; idx < CHUNK*16; idx += 512){
        const int t = idx >> 4, c4 = (idx & 15) * 4;
        const size_t go = (size_t)(row0 + t)*HH + h*HD + c4;
        *reinterpret_cast<float4*>(&g_attn[go]) = *reinterpret_cast<const float4*>(&outs[t*HD + c4]);
    }
}

// ---------------- LayerNorm + SiLU-gate + bf16 split (fused) -----------------
__global__ void __launch_bounds__(256) ln_gate_kernel(
    const float* __restrict__ lng, const float* __restrict__ lnb)
{
    const int r = blockIdx.x, tid = threadIdx.x;
    __shared__ float xs[HH];
    __shared__ float red[8];
    const float* row = g_attn + (size_t)r*HH;
    float s = 0.f;
    for (int i=tid;i<HH;i+=256){ float v = row[i]; xs[i] = v; s += v; }
    #pragma unroll
    for (int o=16;o;o>>=1) s += __shfl_xor_sync(0xffffffffu, s, o);
    if ((tid & 31) == 0) red[tid>>5] = s;
    __syncthreads();
    float tot = red[0]+red[1]+red[2]+red[3]+red[4]+red[5]+red[6]+red[7];
    const float mu = tot * (1.f/HH);
    __syncthreads();
    float vsum = 0.f;
    for (int i=tid;i<HH;i+=256){ float d = xs[i]-mu; vsum = fmaf(d,d,vsum); }
    #pragma unroll
    for (int o=16;o;o>>=1) vsum += __shfl_xor_sync(0xffffffffu, vsum, o);
    if ((tid & 31) == 0) red[tid>>5] = vsum;
    __syncthreads();
    float vtot = red[0]+red[1]+red[2]+red[3]+red[4]+red[5]+red[6]+red[7];
    const float rstd = rsqrtf(vtot*(1.f/HH) + 1e-5f);
    for (int i=tid*4;i<HH;i+=256*4){
        float4 gv = *reinterpret_cast<const float4*>(g_g + (size_t)r*HH + i);
        float4 yv;
        yv.x = ((xs[i+0]-mu)*rstd*lng[i+0] + lnb[i+0]) * gv.x;
        yv.y = ((xs[i+1]-mu)*rstd*lng[i+1] + lnb[i+1]) * gv.y;
        yv.z = ((xs[i+2]-mu)*rstd*lng[i+2] + lnb[i+2]) * gv.z;
        yv.w = ((xs[i+3]-mu)*rstd*lng[i+3] + lnb[i+3]) * gv.w;
        split4(yv, g_ahi + (size_t)r*HH + i, g_alo + (size_t)r*HH + i);
    }
}

// ---------------- launch -----------------------------------------------------
extern "C" void kernel_launch(void* const* d_in, const int* in_sizes, int n_in,
                              void* d_out, int out_size)
{
    const float* x   = (const float*)d_in[0];
    const float* Wq  = (const float*)d_in[1];
    const float* Wk  = (const float*)d_in[2];
    const float* Wv  = (const float*)d_in[3];
    const float* Wa  = (const float*)d_in[4];
    const float* ba  = (const float*)d_in[5];
    const float* Wb  = (const float*)d_in[6];
    const float* bb  = (const float*)d_in[7];
    const float* Wg  = (const float*)d_in[8];
    const float* Wo  = (const float*)d_in[9];
    const float* lng = (const float*)d_in[10];
    const float* lnb = (const float*)d_in[11];
    float* out = (float*)d_out;

    cudaFuncSetAttribute(mm_kernel, cudaFuncAttributeMaxDynamicSharedMemorySize, MM_SMEM);
    cudaFuncSetAttribute(pass2_kernel, cudaFuncAttributeMaxDynamicSharedMemorySize, P2_SMEM);

    const int XN4 = (NROWS*HH)/4;
    const int WN4 = (HH*HH)/4;
    cvt_x_kernel<<<(XN4+255)/256, 256>>>(x);                       // 1
    cvt_w_kernel<<<(5*WN4+255)/256, 256>>>(Wq, Wk, Wv, Wg, Wo);    // 2
    ab_kernel<<<NROWS, 256>>>(x, Wa, ba, Wb, bb);                  // 3
    mm_kernel<<<dim3(32, 64), 256, MM_SMEM>>>(0, nullptr);         // 4
    l2qk_kernel<<<(2*NROWS*NH)/8, 256>>>();                        // 5
    pass1_kernel<<<dim3(NCHUNK, BHDIM), 512>>>();                  // 6  <- ncu capture
    scan_kernel<<<BHDIM, 512>>>();                                 // 7
    pass2_kernel<<<dim3(NCHUNK, BHDIM), 512, P2_SMEM>>>();         // 8
    ln_gate_kernel<<<NROWS, 256>>>(lng, lnb);                      // 9
    mm_kernel<<<dim3(8, 64), 256, MM_SMEM>>>(1, out);              // 10
}